// round 13
// baseline (speedup 1.0000x reference)
#include <cuda_runtime.h>
#include <cuda_bf16.h>
#include <math.h>
#include <stdint.h>

#define NN    8192
#define DIM   64
#define TOPK  64
#define CCAP  256
#define SCAP  160
#define SCREEN 0.49f
#define TS    128
#define PAD   72            // b16 pitch (144B rows, 16B aligned, ldsm conflict-free)
#define NTILE (NN / TS)     // 64
#define NJOBS (NTILE * (NTILE + 1) / 2)   // 2080
#define PBLK  296           // persistent grid: 2 per SM, one wave

// ---- static device scratch ----
__device__ float         g_hn[NN * DIM];
__device__ __nv_bfloat16 g_hnbf[NN * DIM];
__device__ int           g_candJ[NN * CCAP];
__device__ int           g_ccnt[NN];

// ---------------------------------------------------------------------------
// helpers
// ---------------------------------------------------------------------------
__device__ __forceinline__ uint32_t smem_u32(const void* p) {
    uint32_t a;
    asm("{ .reg .u64 t; cvta.to.shared.u64 t, %1; cvt.u32.u64 %0, t; }"
        : "=r"(a) : "l"(p));
    return a;
}
__device__ __forceinline__ void ldsm4(uint32_t* r, uint32_t addr) {
    asm volatile("ldmatrix.sync.aligned.m8n8.x4.shared.b16 {%0,%1,%2,%3}, [%4];"
                 : "=r"(r[0]), "=r"(r[1]), "=r"(r[2]), "=r"(r[3]) : "r"(addr));
}
__device__ __forceinline__ void mma16816(float* c, const uint32_t* a, const uint32_t* b) {
    asm volatile(
        "mma.sync.aligned.m16n8k16.row.col.f32.bf16.bf16.f32 "
        "{%0,%1,%2,%3}, {%4,%5,%6,%7}, {%8,%9}, {%0,%1,%2,%3};"
        : "+f"(c[0]), "+f"(c[1]), "+f"(c[2]), "+f"(c[3])
        : "r"(a[0]), "r"(a[1]), "r"(a[2]), "r"(a[3]), "r"(b[0]), "r"(b[1]));
}
__device__ __forceinline__ void cpasync16(uint32_t saddr, const void* gptr) {
    asm volatile("cp.async.cg.shared.global [%0], [%1], 16;"
                 :: "r"(saddr), "l"(gptr));
}
__device__ __forceinline__ void cpasync_commit() {
    asm volatile("cp.async.commit_group;");
}
template <int N>
__device__ __forceinline__ void cpasync_wait() {
    asm volatile("cp.async.wait_group %0;" :: "n"(N));
}

// ---------------------------------------------------------------------------
// Kernel 1: hn (unchanged, proven)
// ---------------------------------------------------------------------------
__global__ void __launch_bounds__(256) hn_kernel(
    const int* __restrict__ idx,
    const float* __restrict__ emb,
    const float* __restrict__ W,
    const float* __restrict__ bias,
    float* __restrict__ H)
{
    __shared__ float WsT[64 * 72];
    __shared__ float xs[16][64];
    __shared__ int   s_src[16];
    __shared__ float s_bias[64];

    int t = threadIdx.x;

    ((float4*)H)[blockIdx.x * 256 + t] = make_float4(0.f, 0.f, 0.f, 0.f);
    if (blockIdx.x < 8)
        ((int4*)g_ccnt)[blockIdx.x * 256 + t] = make_int4(0, 0, 0, 0);

    if (t < 16) s_src[t] = idx[blockIdx.x * 16 + t] & (NN - 1);
    if (t < 64) s_bias[t] = bias[t];

    #pragma unroll
    for (int q = 0; q < 16; q++) {
        int e = q * 256 + t;
        WsT[(e & 63) * 72 + (e >> 6)] = W[e];
    }
    __syncthreads();

    #pragma unroll
    for (int q = 0; q < 4; q++) {
        int e = q * 256 + t;
        int r = e >> 6, k = e & 63;
        xs[r][k] = emb[s_src[r] * DIM + k];
    }
    __syncthreads();

    int r  = t >> 4;
    int d0 = (t & 15) * 4;

    float a0 = s_bias[d0], a1 = s_bias[d0 + 1], a2 = s_bias[d0 + 2], a3 = s_bias[d0 + 3];
    #pragma unroll
    for (int k = 0; k < 64; k++) {
        float  xv = xs[r][k];
        float4 w4 = *(const float4*)&WsT[k * 72 + d0];
        a0 += xv * w4.x; a1 += xv * w4.y; a2 += xv * w4.z; a3 += xv * w4.w;
    }

    float h0 = tanhf(3.0f * a0), h1 = tanhf(3.0f * a1);
    float h2 = tanhf(3.0f * a2), h3 = tanhf(3.0f * a3);

    float sq = h0 * h0 + h1 * h1 + h2 * h2 + h3 * h3;
    #pragma unroll
    for (int o = 8; o; o >>= 1)
        sq += __shfl_xor_sync(0xffffffffu, sq, o);

    float nrm = fmaxf(sqrtf(sq), 1e-8f);
    float v0 = h0 / nrm, v1 = h1 / nrm, v2 = h2 / nrm, v3 = h3 / nrm;

    int row = blockIdx.x * 16 + r;
    *(float4*)&g_hn[row * DIM + d0] = make_float4(v0, v1, v2, v3);

    __nv_bfloat162* bp = (__nv_bfloat162*)&g_hnbf[row * DIM + d0];
    bp[0] = __nv_bfloat162(__float2bfloat16(v0), __float2bfloat16(v1));
    bp[1] = __nv_bfloat162(__float2bfloat16(v2), __float2bfloat16(v3));
}

// ---------------------------------------------------------------------------
// Kernel 2: persistent bf16 HMMA screen, single wave (296 blocks), each block
// handles 7-8 consecutive triangular jobs with cp.async double-buffered tiles.
// ---------------------------------------------------------------------------
__device__ __forceinline__ void screen_push(int gi, int gj, float v, bool diag)
{
    if (v >= SCREEN) {
        if (!diag || gj > gi) {
            int p = atomicAdd(&g_ccnt[gi], 1);
            if (p < CCAP) g_candJ[gi * CCAP + p] = gj;
            p = atomicAdd(&g_ccnt[gj], 1);
            if (p < CCAP) g_candJ[gj * CCAP + p] = gi;
        } else if (gj == gi) {
            int p = atomicAdd(&g_ccnt[gi], 1);
            if (p < CCAP) g_candJ[gi * CCAP + p] = gi;
        }
    }
}

extern __shared__ __nv_bfloat16 smemP[];   // [2][TS*PAD] A then [2][TS*PAD] B

__global__ void __launch_bounds__(256, 2) sim_mma_kernel()
{
    __nv_bfloat16* sA[2] = { smemP,            smemP + TS * PAD };
    __nv_bfloat16* sB[2] = { smemP + 2*TS*PAD, smemP + 3*TS*PAD };

    int t = threadIdx.x, wid = t >> 5, l = t & 31;
    int b = blockIdx.x;

    // contiguous job chunk: blocks 0..7 get 8 jobs, rest get 7
    int jstart = b * 7 + (b < 8 ? b : 8);
    int jcount = 7 + (b < 8 ? 1 : 0);

    // decode jstart -> (ti, tj)
    int rem = jstart, ti = 0;
    while (rem >= NTILE - ti) { rem -= NTILE - ti; ti++; }
    int tj = ti + rem;

    const char* hb = (const char*)g_hnbf;

    // prefetch job 0 into buffer 0
    {
        int ib = ti * TS, jb = tj * TS;
        #pragma unroll
        for (int q = 0; q < 4; q++) {
            int id = q * 256 + t;
            int row = id >> 3, c = (id & 7) * 16;
            cpasync16(smem_u32((char*)sA[0] + row * (PAD*2) + c),
                      hb + (size_t)(ib + row) * 128 + c);
            cpasync16(smem_u32((char*)sB[0] + row * (PAD*2) + c),
                      hb + (size_t)(jb + row) * 128 + c);
        }
    }
    cpasync_commit();

    int cti = ti, ctj = tj;
    for (int q = 0; q < jcount; q++) {
        // advance to next job coords
        int nti = cti, ntj = ctj + 1;
        if (ntj == NTILE) { nti = cti + 1; ntj = nti; }

        // prefetch next job into alternate buffer
        if (q + 1 < jcount) {
            int ib = nti * TS, jb = ntj * TS;
            int nb = (q + 1) & 1;
            #pragma unroll
            for (int qq = 0; qq < 4; qq++) {
                int id = qq * 256 + t;
                int row = id >> 3, c = (id & 7) * 16;
                cpasync16(smem_u32((char*)sA[nb] + row * (PAD*2) + c),
                          hb + (size_t)(ib + row) * 128 + c);
                cpasync16(smem_u32((char*)sB[nb] + row * (PAD*2) + c),
                          hb + (size_t)(jb + row) * 128 + c);
            }
        }
        cpasync_commit();
        cpasync_wait<1>();      // current job's tiles resident
        __syncthreads();

        // ---- compute current job ----
        int cb = q & 1;
        int ib = cti * TS, jb = ctj * TS;

        int wr = wid >> 2, wc = wid & 3;
        int R0 = wr * 64, C0 = wc * 32;

        float acc[4][4][4];
        #pragma unroll
        for (int mt = 0; mt < 4; mt++)
            #pragma unroll
            for (int nt = 0; nt < 4; nt++)
                #pragma unroll
                for (int e = 0; e < 4; e++) acc[mt][nt][e] = 0.0f;

        uint32_t aBase = smem_u32(sA[cb]);
        uint32_t bBase = smem_u32(sB[cb]);

        int lr    = l & 7;
        int khalf = (l >> 3) & 1;
        int kq    = l >> 4;

        #pragma unroll
        for (int ks = 0; ks < 4; ks++) {
            int k0 = ks * 16;

            uint32_t af[4][4];
            #pragma unroll
            for (int mt = 0; mt < 4; mt++) {
                uint32_t addr = aBase +
                    (uint32_t)(((R0 + mt * 16 + lr + khalf * 8) * PAD + k0 + kq * 8) * 2);
                ldsm4(af[mt], addr);
            }

            uint32_t bf[4][2];
            #pragma unroll
            for (int np = 0; np < 2; np++) {
                uint32_t r4[4];
                uint32_t addr = bBase +
                    (uint32_t)(((C0 + np * 16 + kq * 8 + lr) * PAD + k0 + khalf * 8) * 2);
                ldsm4(r4, addr);
                bf[np * 2 + 0][0] = r4[0]; bf[np * 2 + 0][1] = r4[1];
                bf[np * 2 + 1][0] = r4[2]; bf[np * 2 + 1][1] = r4[3];
            }

            #pragma unroll
            for (int mt = 0; mt < 4; mt++)
                #pragma unroll
                for (int nt = 0; nt < 4; nt++)
                    mma16816(acc[mt][nt], af[mt], bf[nt]);
        }

        // ---- ballot early-out epilogue ----
        bool diag = (cti == ctj);
        int gr = l >> 2, tg = l & 3;
        #pragma unroll
        for (int mt = 0; mt < 4; mt++) {
            float mx = acc[mt][0][0];
            #pragma unroll
            for (int nt = 0; nt < 4; nt++)
                #pragma unroll
                for (int e = 0; e < 4; e++)
                    mx = fmaxf(mx, acc[mt][nt][e]);

            if (__any_sync(0xffffffffu, mx >= SCREEN)) {
                int gi0 = ib + R0 + mt * 16 + gr;
                #pragma unroll
                for (int nt = 0; nt < 4; nt++) {
                    int gj0 = jb + C0 + nt * 8 + tg * 2;
                    float* c = acc[mt][nt];
                    screen_push(gi0,     gj0,     c[0], diag);
                    screen_push(gi0,     gj0 + 1, c[1], diag);
                    screen_push(gi0 + 8, gj0,     c[2], diag);
                    screen_push(gi0 + 8, gj0 + 1, c[3], diag);
                }
            }
        }

        __syncthreads();   // all reads of buf[cb] done before it is overwritten
        cti = nti; ctj = ntj;
    }
}

// ---------------------------------------------------------------------------
// Kernel 3: exact fp32 recheck + per-row top-64 (unchanged, proven)
// ---------------------------------------------------------------------------
__global__ void __launch_bounds__(256) topk_kernel(float* __restrict__ H)
{
    __shared__ float sV[8][SCAP];
    __shared__ int   sJ[8][SCAP];

    int t = threadIdx.x, w = t >> 5, l = t & 31;
    int r = blockIdx.x * 8 + w;
    const float* __restrict__ hn = g_hn;

    int m = g_ccnt[r];
    if (m > CCAP) m = CCAP;

    float a1 = hn[r * DIM + l];
    float a2 = hn[r * DIM + 32 + l];

    int cnt = 0;
    for (int p = 0; p < m; p++) {
        int j = g_candJ[r * CCAP + p];
        float s = a1 * hn[j * DIM + l] + a2 * hn[j * DIM + 32 + l];
        #pragma unroll
        for (int o = 16; o; o >>= 1)
            s += __shfl_xor_sync(0xffffffffu, s, o);
        if (s >= 0.5f && cnt < SCAP) {
            if (l == 0) { sV[w][cnt] = s; sJ[w][cnt] = j; }
            cnt++;
        }
    }
    __syncwarp();

    float* kv = sV[w];
    int*   kj = sJ[w];
    int nsel = cnt < TOPK ? cnt : TOPK;

    for (int s = 0; s < nsel; s++) {
        float bv = -1.0f; int bj = NN; int bp = -1;
        for (int p = l; p < cnt; p += 32) {
            float v = kv[p]; int j = kj[p];
            if (v > bv || (v == bv && j < bj)) { bv = v; bj = j; bp = p; }
        }
        #pragma unroll
        for (int o = 16; o; o >>= 1) {
            float ov = __shfl_xor_sync(0xffffffffu, bv, o);
            int   oj = __shfl_xor_sync(0xffffffffu, bj, o);
            int   op = __shfl_xor_sync(0xffffffffu, bp, o);
            if (ov > bv || (ov == bv && oj < bj)) { bv = ov; bj = oj; bp = op; }
        }
        if (l == 0) {
            H[s * NN + bj] = 1.0f;
            kv[bp] = -1.0f;
        }
        __syncwarp();
    }

    if (l == 0) {
        int s = nsel;
        int j = 0;
        while (s < TOPK) {
            bool kept = false;
            for (int p = 0; p < cnt; p++)
                if (kj[p] == j) { kept = true; break; }
            if (!kept) { H[s * NN + j] = 1.0f; s++; }
            j++;
        }
    }
}

// ---------------------------------------------------------------------------
// launch
// ---------------------------------------------------------------------------
extern "C" void kernel_launch(void* const* d_in, const int* in_sizes, int n_in,
                              void* d_out, int out_size)
{
    const int* idx    = (const int*)d_in[0];
    const float* emb  = (const float*)d_in[1];
    const float* W    = (const float*)d_in[2];
    const float* bias = (const float*)d_in[3];
    float* H          = (float*)d_out;

    const int smem_bytes = 4 * TS * PAD * 2;   // 2xA + 2xB = 73,728 B
    cudaFuncSetAttribute(sim_mma_kernel,
                         cudaFuncAttributeMaxDynamicSharedMemorySize, smem_bytes);

    hn_kernel<<<NN / 16, 256>>>(idx, emb, W, bias, H);
    sim_mma_kernel<<<PBLK, 256, smem_bytes>>>();
    topk_kernel<<<NN / 8, 256>>>(H);
}

// round 15
// speedup vs baseline: 1.6270x; 1.6270x over previous
#include <cuda_runtime.h>
#include <cuda_bf16.h>
#include <math.h>
#include <stdint.h>

#define NN    8192
#define DIM   64
#define TOPK  64
#define CCAP  256
#define SCAP  160
#define SCREEN 0.49f
#define TS    128
#define PAD   72
#define NTILE (NN / TS)
#define NJOBS (NTILE * (NTILE + 1) / 2)

__device__ float         g_hn[NN * DIM];
__device__ __nv_bfloat16 g_hnbf[NN * DIM];
__device__ int           g_candJ[NN * CCAP];
__device__ int           g_ccnt[NN];

// ---------------------------------------------------------------------------
__device__ __forceinline__ uint32_t smem_u32(const void* p) {
    uint32_t a;
    asm("{ .reg .u64 t; cvta.to.shared.u64 t, %1; cvt.u32.u64 %0, t; }"
        : "=r"(a) : "l"(p));
    return a;
}
__device__ __forceinline__ void ldsm4(uint32_t* r, uint32_t addr) {
    asm volatile("ldmatrix.sync.aligned.m8n8.x4.shared.b16 {%0,%1,%2,%3}, [%4];"
                 : "=r"(r[0]), "=r"(r[1]), "=r"(r[2]), "=r"(r[3]) : "r"(addr));
}
__device__ __forceinline__ void mma16816(float* c, const uint32_t* a, const uint32_t* b) {
    asm volatile(
        "mma.sync.aligned.m16n8k16.row.col.f32.bf16.bf16.f32 "
        "{%0,%1,%2,%3}, {%4,%5,%6,%7}, {%8,%9}, {%0,%1,%2,%3};"
        : "+f"(c[0]), "+f"(c[1]), "+f"(c[2]), "+f"(c[3])
        : "r"(a[0]), "r"(a[1]), "r"(a[2]), "r"(a[3]), "r"(b[0]), "r"(b[1]));
}

// ---------------------------------------------------------------------------
// Kernel 1: hn (unchanged, proven)
// ---------------------------------------------------------------------------
__global__ void __launch_bounds__(256) hn_kernel(
    const int* __restrict__ idx,
    const float* __restrict__ emb,
    const float* __restrict__ W,
    const float* __restrict__ bias,
    float* __restrict__ H)
{
    __shared__ float WsT[64 * 72];
    __shared__ float xs[16][64];
    __shared__ int   s_src[16];
    __shared__ float s_bias[64];

    int t = threadIdx.x;

    ((float4*)H)[blockIdx.x * 256 + t] = make_float4(0.f, 0.f, 0.f, 0.f);
    if (blockIdx.x < 8)
        ((int4*)g_ccnt)[blockIdx.x * 256 + t] = make_int4(0, 0, 0, 0);

    if (t < 16) s_src[t] = idx[blockIdx.x * 16 + t] & (NN - 1);
    if (t < 64) s_bias[t] = bias[t];

    #pragma unroll
    for (int q = 0; q < 16; q++) {
        int e = q * 256 + t;
        WsT[(e & 63) * 72 + (e >> 6)] = W[e];
    }
    __syncthreads();

    #pragma unroll
    for (int q = 0; q < 4; q++) {
        int e = q * 256 + t;
        int r = e >> 6, k = e & 63;
        xs[r][k] = emb[s_src[r] * DIM + k];
    }
    __syncthreads();

    int r  = t >> 4;
    int d0 = (t & 15) * 4;

    float a0 = s_bias[d0], a1 = s_bias[d0 + 1], a2 = s_bias[d0 + 2], a3 = s_bias[d0 + 3];
    #pragma unroll
    for (int k = 0; k < 64; k++) {
        float  xv = xs[r][k];
        float4 w4 = *(const float4*)&WsT[k * 72 + d0];
        a0 += xv * w4.x; a1 += xv * w4.y; a2 += xv * w4.z; a3 += xv * w4.w;
    }

    float h0 = tanhf(3.0f * a0), h1 = tanhf(3.0f * a1);
    float h2 = tanhf(3.0f * a2), h3 = tanhf(3.0f * a3);

    float sq = h0 * h0 + h1 * h1 + h2 * h2 + h3 * h3;
    #pragma unroll
    for (int o = 8; o; o >>= 1)
        sq += __shfl_xor_sync(0xffffffffu, sq, o);

    float nrm = fmaxf(sqrtf(sq), 1e-8f);
    float v0 = h0 / nrm, v1 = h1 / nrm, v2 = h2 / nrm, v3 = h3 / nrm;

    int row = blockIdx.x * 16 + r;
    *(float4*)&g_hn[row * DIM + d0] = make_float4(v0, v1, v2, v3);

    __nv_bfloat162* bp = (__nv_bfloat162*)&g_hnbf[row * DIM + d0];
    bp[0] = __nv_bfloat162(__float2bfloat16(v0), __float2bfloat16(v1));
    bp[1] = __nv_bfloat162(__float2bfloat16(v2), __float2bfloat16(v3));
}

// ---------------------------------------------------------------------------
// Kernel 2: bf16 HMMA screen (GEMM core identical to R11); aggregated
// mask-based epilogue: one atomicAdd per surviving row/col group.
// ---------------------------------------------------------------------------
__global__ void __launch_bounds__(256) sim_mma_kernel()
{
    __shared__ __nv_bfloat16 sA[TS * PAD];
    __shared__ __nv_bfloat16 sB[TS * PAD];

    int b = blockIdx.x, ti = 0;
    while (b >= NTILE - ti) { b -= NTILE - ti; ti++; }
    int tj = ti + b;
    int ib = ti * TS, jb = tj * TS;

    int t = threadIdx.x, wid = t >> 5, l = t & 31;

    const __nv_bfloat16* hb = g_hnbf;
    #pragma unroll
    for (int q = 0; q < 4; q++) {
        int id  = q * 256 + t;
        int row = id >> 3, c8 = (id & 7) * 8;
        *(uint4*)(sA + row * PAD + c8) = *(const uint4*)(hb + (ib + row) * DIM + c8);
        *(uint4*)(sB + row * PAD + c8) = *(const uint4*)(hb + (jb + row) * DIM + c8);
    }
    __syncthreads();

    int wr = wid >> 2, wc = wid & 3;
    int R0 = wr * 64, C0 = wc * 32;

    float acc[4][4][4];
    #pragma unroll
    for (int mt = 0; mt < 4; mt++)
        #pragma unroll
        for (int nt = 0; nt < 4; nt++)
            #pragma unroll
            for (int e = 0; e < 4; e++) acc[mt][nt][e] = 0.0f;

    uint32_t aBase = smem_u32(sA);
    uint32_t bBase = smem_u32(sB);

    int lr    = l & 7;
    int khalf = (l >> 3) & 1;
    int kq    = l >> 4;

    #pragma unroll
    for (int ks = 0; ks < 4; ks++) {
        int k0 = ks * 16;

        uint32_t af[4][4];
        #pragma unroll
        for (int mt = 0; mt < 4; mt++) {
            uint32_t addr = aBase +
                (uint32_t)(((R0 + mt * 16 + lr + khalf * 8) * PAD + k0 + kq * 8) * 2);
            ldsm4(af[mt], addr);
        }

        uint32_t bf[4][2];
        #pragma unroll
        for (int np = 0; np < 2; np++) {
            uint32_t r4[4];
            uint32_t addr = bBase +
                (uint32_t)(((C0 + np * 16 + kq * 8 + lr) * PAD + k0 + khalf * 8) * 2);
            ldsm4(r4, addr);
            bf[np * 2 + 0][0] = r4[0]; bf[np * 2 + 0][1] = r4[1];
            bf[np * 2 + 1][0] = r4[2]; bf[np * 2 + 1][1] = r4[3];
        }

        #pragma unroll
        for (int mt = 0; mt < 4; mt++)
            #pragma unroll
            for (int nt = 0; nt < 4; nt++)
                mma16816(acc[mt][nt], af[mt], bf[nt]);
    }

    // ---- aggregated epilogue ----
    bool diag = (ti == tj);
    int gr = l >> 2, tg = l & 3;
    int colBase = jb + C0 + tg * 2;

    // row-wise: one atomicAdd per (mt, rh) group with survivors
    #pragma unroll
    for (int mt = 0; mt < 4; mt++) {
        #pragma unroll
        for (int rh = 0; rh < 2; rh++) {
            int gi = ib + R0 + mt * 16 + gr + rh * 8;
            uint32_t mask = 0;
            #pragma unroll
            for (int nt = 0; nt < 4; nt++) {
                #pragma unroll
                for (int eb = 0; eb < 2; eb++) {
                    float v = acc[mt][nt][rh * 2 + eb];
                    int gj = colBase + nt * 8 + eb;
                    bool cond = (v >= SCREEN) && (!diag || gj >= gi);
                    mask |= (cond ? 1u : 0u) << (nt * 2 + eb);
                }
            }
            if (mask) {
                int n = __popc(mask);
                int base = atomicAdd(&g_ccnt[gi], n);
                while (mask) {
                    int bit = __ffs(mask) - 1;
                    mask &= mask - 1;
                    int gj = colBase + (bit >> 1) * 8 + (bit & 1);
                    if (base < CCAP) g_candJ[gi * CCAP + base] = gj;
                    base++;
                }
            }
        }
    }
    // column-wise: one atomicAdd per (nt, eb) group with survivors
    #pragma unroll
    for (int nt = 0; nt < 4; nt++) {
        #pragma unroll
        for (int eb = 0; eb < 2; eb++) {
            int gj = colBase + nt * 8 + eb;
            uint32_t mask = 0;
            #pragma unroll
            for (int mt = 0; mt < 4; mt++) {
                #pragma unroll
                for (int rh = 0; rh < 2; rh++) {
                    float v = acc[mt][nt][rh * 2 + eb];
                    int gi = ib + R0 + mt * 16 + gr + rh * 8;
                    bool cond = (v >= SCREEN) && (!diag || gj > gi);
                    mask |= (cond ? 1u : 0u) << (mt * 2 + rh);
                }
            }
            if (mask) {
                int n = __popc(mask);
                int base = atomicAdd(&g_ccnt[gj], n);
                while (mask) {
                    int bit = __ffs(mask) - 1;
                    mask &= mask - 1;
                    int gi = ib + R0 + (bit >> 1) * 16 + gr + (bit & 1) * 8;
                    if (base < CCAP) g_candJ[gj * CCAP + base] = gi;
                    base++;
                }
            }
        }
    }
}

// ---------------------------------------------------------------------------
// Kernel 3: parallel recheck + u64-key selection + bitmask fill.
// One warp per row, 8 rows per block.
// ---------------------------------------------------------------------------
__global__ void __launch_bounds__(256) topk_kernel(float* __restrict__ H)
{
    __shared__ float              sR[8][64];
    __shared__ unsigned long long sK[8][SCAP];
    __shared__ uint32_t           sMask[8][256];

    int t = threadIdx.x, w = t >> 5, l = t & 31;
    int r = blockIdx.x * 8 + w;
    const float* __restrict__ hn = g_hn;

    // own row into shared; zero bitmask
    sR[w][l]      = hn[r * DIM + l];
    sR[w][32 + l] = hn[r * DIM + 32 + l];
    #pragma unroll
    for (int c = 0; c < 8; c++) sMask[w][c * 32 + l] = 0;
    __syncwarp();

    int m = g_ccnt[r];
    if (m > CCAP) m = CCAP;

    // parallel recheck: one candidate per lane, batches of 32
    int cnt = 0;
    for (int base = 0; base < m; base += 32) {
        int p = base + l;
        bool valid = p < m;
        int j = 0;
        float s = 0.0f;
        if (valid) {
            j = g_candJ[r * CCAP + p];
            const float4* row = (const float4*)(hn + j * DIM);
            float4 av[16];
            #pragma unroll
            for (int q = 0; q < 16; q++) av[q] = row[q];
            const float4* own = (const float4*)sR[w];
            #pragma unroll
            for (int q = 0; q < 16; q++) {
                float4 b4 = own[q];
                s += av[q].x * b4.x + av[q].y * b4.y
                   + av[q].z * b4.z + av[q].w * b4.w;
            }
        }
        bool surv = valid && (s >= 0.5f);
        uint32_t bal = __ballot_sync(0xffffffffu, surv);
        int rank = __popc(bal & ((1u << l) - 1u));
        if (surv) {
            int pos = cnt + rank;
            if (pos < SCAP) {
                sK[w][pos] = (((unsigned long long)__float_as_uint(s)) << 32)
                           | (uint32_t)(8191 - j);
                atomicOr(&sMask[w][j >> 5], 1u << (j & 31));
            }
        }
        cnt += __popc(bal);
    }
    __syncwarp();
    if (cnt > SCAP) cnt = SCAP;
    int nsel = cnt < TOPK ? cnt : TOPK;

    // selection: repeated warp max over u64 keys (value desc, index asc)
    for (int s = 0; s < nsel; s++) {
        unsigned long long lb = 0; int bpos = -1;
        for (int p = l; p < cnt; p += 32) {
            unsigned long long k = sK[w][p];
            if (k > lb) { lb = k; bpos = p; }
        }
        unsigned long long gb = lb;
        #pragma unroll
        for (int o = 16; o; o >>= 1) {
            unsigned long long ok = __shfl_xor_sync(0xffffffffu, gb, o);
            if (ok > gb) gb = ok;
        }
        if (bpos >= 0 && lb == gb) sK[w][bpos] = 0;   // unique owner clears
        if (l == 0) {
            int j = 8191 - (int)(uint32_t)(gb & 0xFFFFFFFFu);
            H[s * NN + j] = 1.0f;
        }
        __syncwarp();
    }

    // fill remaining slots with zeros (ascending j, skipping survivors)
    int s = nsel;
    for (int c = 0; c < 256 && s < TOPK; c++) {
        uint32_t word = sMask[w][c];
        uint32_t zmask = ~word;
        int nz = __popc(zmask);
        int take = TOPK - s; if (take > nz) take = nz;
        int rank = __popc(zmask & ((1u << l) - 1u));
        if (!((word >> l) & 1u) && rank < take)
            H[(s + rank) * NN + (c * 32 + l)] = 1.0f;
        s += nz;
    }
}

// ---------------------------------------------------------------------------
extern "C" void kernel_launch(void* const* d_in, const int* in_sizes, int n_in,
                              void* d_out, int out_size)
{
    const int* idx    = (const int*)d_in[0];
    const float* emb  = (const float*)d_in[1];
    const float* W    = (const float*)d_in[2];
    const float* bias = (const float*)d_in[3];
    float* H          = (float*)d_out;

    hn_kernel<<<NN / 16, 256>>>(idx, emb, W, bias, H);
    sim_mma_kernel<<<NJOBS, 256>>>();
    topk_kernel<<<NN / 8, 256>>>(H);
}

// round 16
// speedup vs baseline: 1.7630x; 1.0836x over previous
#include <cuda_runtime.h>
#include <cuda_bf16.h>
#include <math.h>
#include <stdint.h>

#define NN    8192
#define DIM   64
#define TOPK  64
#define CCAP  256
#define SCAP  160
#define SCREEN 0.49f
#define TS    128
#define PAD   72
#define NTILE (NN / TS)
#define NJOBS (NTILE * (NTILE + 1) / 2)

__device__ float         g_hn[NN * DIM];
__device__ __nv_bfloat16 g_hnbf[NN * DIM];
__device__ int           g_candJ[NN * CCAP];
__device__ int           g_ccnt[NN];

// ---------------------------------------------------------------------------
__device__ __forceinline__ uint32_t smem_u32(const void* p) {
    uint32_t a;
    asm("{ .reg .u64 t; cvta.to.shared.u64 t, %1; cvt.u32.u64 %0, t; }"
        : "=r"(a) : "l"(p));
    return a;
}
__device__ __forceinline__ void ldsm4(uint32_t* r, uint32_t addr) {
    asm volatile("ldmatrix.sync.aligned.m8n8.x4.shared.b16 {%0,%1,%2,%3}, [%4];"
                 : "=r"(r[0]), "=r"(r[1]), "=r"(r[2]), "=r"(r[3]) : "r"(addr));
}
__device__ __forceinline__ void mma16816(float* c, const uint32_t* a, const uint32_t* b) {
    asm volatile(
        "mma.sync.aligned.m16n8k16.row.col.f32.bf16.bf16.f32 "
        "{%0,%1,%2,%3}, {%4,%5,%6,%7}, {%8,%9}, {%0,%1,%2,%3};"
        : "+f"(c[0]), "+f"(c[1]), "+f"(c[2]), "+f"(c[3])
        : "r"(a[0]), "r"(a[1]), "r"(a[2]), "r"(a[3]), "r"(b[0]), "r"(b[1]));
}

// ---------------------------------------------------------------------------
// Kernel 1: hn, fat blocks — 128 blocks x 64 rows. W loaded once per block
// (4x fewer redundant loads), xs pitch 68 (bank-conflict free), 16 dims/thread.
// Also zeroes H and g_ccnt. idx is int32.
// ---------------------------------------------------------------------------
__global__ void __launch_bounds__(256) hn_kernel(
    const int* __restrict__ idx,
    const float* __restrict__ emb,
    const float* __restrict__ W,
    const float* __restrict__ bias,
    float* __restrict__ H)
{
    __shared__ float WsT[64 * 68];    // WsT[k][d], pitch 68
    __shared__ float xs[64][68];      // xs[r][k],  pitch 68
    __shared__ int   s_src[64];
    __shared__ float s_bias[64];

    int t = threadIdx.x;

    // zero H: 128 blocks x 256 threads x 4 float4 = 524288 floats (exact)
    float4 z4 = make_float4(0.f, 0.f, 0.f, 0.f);
    #pragma unroll
    for (int q = 0; q < 4; q++)
        ((float4*)H)[(blockIdx.x * 4 + q) * 256 + t] = z4;
    if (blockIdx.x < 8)
        ((int4*)g_ccnt)[blockIdx.x * 256 + t] = make_int4(0, 0, 0, 0);

    if (t < 64) {
        s_src[t]  = idx[blockIdx.x * 64 + t] & (NN - 1);
        s_bias[t] = bias[t];
    }
    // W[d][k] -> WsT[k][d]
    #pragma unroll
    for (int q = 0; q < 16; q++) {
        int e = q * 256 + t;
        WsT[(e & 63) * 68 + (e >> 6)] = W[e];
    }
    __syncthreads();

    // xs: 64 rows x 64 k, coalesced (warp covers 32 consecutive k)
    #pragma unroll
    for (int q = 0; q < 16; q++) {
        int e = q * 256 + t;
        int r = e >> 6, k = e & 63;
        xs[r][k] = emb[s_src[r] * DIM + k];
    }
    __syncthreads();

    int r   = t >> 2;         // row 0..63
    int d0  = (t & 3) * 16;   // 16 output dims per thread

    float acc[16];
    #pragma unroll
    for (int d = 0; d < 16; d++) acc[d] = s_bias[d0 + d];

    #pragma unroll 8
    for (int k = 0; k < 64; k++) {
        float xv = xs[r][k];
        #pragma unroll
        for (int dq = 0; dq < 4; dq++) {
            float4 w4 = *(const float4*)&WsT[k * 68 + d0 + dq * 4];
            acc[dq * 4 + 0] += xv * w4.x;
            acc[dq * 4 + 1] += xv * w4.y;
            acc[dq * 4 + 2] += xv * w4.z;
            acc[dq * 4 + 3] += xv * w4.w;
        }
    }

    float h[16];
    float sq = 0.0f;
    #pragma unroll
    for (int d = 0; d < 16; d++) {
        h[d] = tanhf(3.0f * acc[d]);
        sq += h[d] * h[d];
    }
    // reduce over the 4 threads of this row (adjacent lanes)
    sq += __shfl_xor_sync(0xffffffffu, sq, 1);
    sq += __shfl_xor_sync(0xffffffffu, sq, 2);

    float inv = 1.0f / fmaxf(sqrtf(sq), 1e-8f);

    int row = blockIdx.x * 64 + r;
    #pragma unroll
    for (int dq = 0; dq < 4; dq++) {
        float v0 = h[dq*4+0] * inv, v1 = h[dq*4+1] * inv;
        float v2 = h[dq*4+2] * inv, v3 = h[dq*4+3] * inv;
        *(float4*)&g_hn[row * DIM + d0 + dq * 4] = make_float4(v0, v1, v2, v3);
        __nv_bfloat162* bp = (__nv_bfloat162*)&g_hnbf[row * DIM + d0 + dq * 4];
        bp[0] = __nv_bfloat162(__float2bfloat16(v0), __float2bfloat16(v1));
        bp[1] = __nv_bfloat162(__float2bfloat16(v2), __float2bfloat16(v3));
    }
}

// ---------------------------------------------------------------------------
// Kernel 2: bf16 HMMA screen + aggregated epilogue (unchanged from R15 win)
// ---------------------------------------------------------------------------
__global__ void __launch_bounds__(256) sim_mma_kernel()
{
    __shared__ __nv_bfloat16 sA[TS * PAD];
    __shared__ __nv_bfloat16 sB[TS * PAD];

    int b = blockIdx.x, ti = 0;
    while (b >= NTILE - ti) { b -= NTILE - ti; ti++; }
    int tj = ti + b;
    int ib = ti * TS, jb = tj * TS;

    int t = threadIdx.x, wid = t >> 5, l = t & 31;

    const __nv_bfloat16* hb = g_hnbf;
    #pragma unroll
    for (int q = 0; q < 4; q++) {
        int id  = q * 256 + t;
        int row = id >> 3, c8 = (id & 7) * 8;
        *(uint4*)(sA + row * PAD + c8) = *(const uint4*)(hb + (ib + row) * DIM + c8);
        *(uint4*)(sB + row * PAD + c8) = *(const uint4*)(hb + (jb + row) * DIM + c8);
    }
    __syncthreads();

    int wr = wid >> 2, wc = wid & 3;
    int R0 = wr * 64, C0 = wc * 32;

    float acc[4][4][4];
    #pragma unroll
    for (int mt = 0; mt < 4; mt++)
        #pragma unroll
        for (int nt = 0; nt < 4; nt++)
            #pragma unroll
            for (int e = 0; e < 4; e++) acc[mt][nt][e] = 0.0f;

    uint32_t aBase = smem_u32(sA);
    uint32_t bBase = smem_u32(sB);

    int lr    = l & 7;
    int khalf = (l >> 3) & 1;
    int kq    = l >> 4;

    #pragma unroll
    for (int ks = 0; ks < 4; ks++) {
        int k0 = ks * 16;

        uint32_t af[4][4];
        #pragma unroll
        for (int mt = 0; mt < 4; mt++) {
            uint32_t addr = aBase +
                (uint32_t)(((R0 + mt * 16 + lr + khalf * 8) * PAD + k0 + kq * 8) * 2);
            ldsm4(af[mt], addr);
        }

        uint32_t bf[4][2];
        #pragma unroll
        for (int np = 0; np < 2; np++) {
            uint32_t r4[4];
            uint32_t addr = bBase +
                (uint32_t)(((C0 + np * 16 + kq * 8 + lr) * PAD + k0 + khalf * 8) * 2);
            ldsm4(r4, addr);
            bf[np * 2 + 0][0] = r4[0]; bf[np * 2 + 0][1] = r4[1];
            bf[np * 2 + 1][0] = r4[2]; bf[np * 2 + 1][1] = r4[3];
        }

        #pragma unroll
        for (int mt = 0; mt < 4; mt++)
            #pragma unroll
            for (int nt = 0; nt < 4; nt++)
                mma16816(acc[mt][nt], af[mt], bf[nt]);
    }

    bool diag = (ti == tj);
    int gr = l >> 2, tg = l & 3;
    int colBase = jb + C0 + tg * 2;

    #pragma unroll
    for (int mt = 0; mt < 4; mt++) {
        #pragma unroll
        for (int rh = 0; rh < 2; rh++) {
            int gi = ib + R0 + mt * 16 + gr + rh * 8;
            uint32_t mask = 0;
            #pragma unroll
            for (int nt = 0; nt < 4; nt++) {
                #pragma unroll
                for (int eb = 0; eb < 2; eb++) {
                    float v = acc[mt][nt][rh * 2 + eb];
                    int gj = colBase + nt * 8 + eb;
                    bool cond = (v >= SCREEN) && (!diag || gj >= gi);
                    mask |= (cond ? 1u : 0u) << (nt * 2 + eb);
                }
            }
            if (mask) {
                int n = __popc(mask);
                int base = atomicAdd(&g_ccnt[gi], n);
                while (mask) {
                    int bit = __ffs(mask) - 1;
                    mask &= mask - 1;
                    int gj = colBase + (bit >> 1) * 8 + (bit & 1);
                    if (base < CCAP) g_candJ[gi * CCAP + base] = gj;
                    base++;
                }
            }
        }
    }
    #pragma unroll
    for (int nt = 0; nt < 4; nt++) {
        #pragma unroll
        for (int eb = 0; eb < 2; eb++) {
            int gj = colBase + nt * 8 + eb;
            uint32_t mask = 0;
            #pragma unroll
            for (int mt = 0; mt < 4; mt++) {
                #pragma unroll
                for (int rh = 0; rh < 2; rh++) {
                    float v = acc[mt][nt][rh * 2 + eb];
                    int gi = ib + R0 + mt * 16 + gr + rh * 8;
                    bool cond = (v >= SCREEN) && (!diag || gj > gi);
                    mask |= (cond ? 1u : 0u) << (mt * 2 + rh);
                }
            }
            if (mask) {
                int n = __popc(mask);
                int base = atomicAdd(&g_ccnt[gj], n);
                while (mask) {
                    int bit = __ffs(mask) - 1;
                    mask &= mask - 1;
                    int gi = ib + R0 + (bit >> 1) * 16 + gr + (bit & 1) * 8;
                    if (base < CCAP) g_candJ[gj * CCAP + base] = gi;
                    base++;
                }
            }
        }
    }
}

// ---------------------------------------------------------------------------
// Kernel 3: parallel recheck + RANK-BY-COUNTING top-64 + bitmask fill.
// Keys unique -> rank(k) = #{k' > k} reproduces JAX (value desc, index asc).
// ---------------------------------------------------------------------------
__global__ void __launch_bounds__(256) topk_kernel(float* __restrict__ H)
{
    __shared__ float              sR[8][64];
    __shared__ unsigned long long sK[8][SCAP];
    __shared__ uint32_t           sMask[8][256];

    int t = threadIdx.x, w = t >> 5, l = t & 31;
    int r = blockIdx.x * 8 + w;
    const float* __restrict__ hn = g_hn;

    sR[w][l]      = hn[r * DIM + l];
    sR[w][32 + l] = hn[r * DIM + 32 + l];
    #pragma unroll
    for (int c = 0; c < 8; c++) sMask[w][c * 32 + l] = 0;
    __syncwarp();

    int m = g_ccnt[r];
    if (m > CCAP) m = CCAP;

    // parallel recheck: one candidate per lane
    int cnt = 0;
    for (int base = 0; base < m; base += 32) {
        int p = base + l;
        bool valid = p < m;
        int j = 0;
        float s = 0.0f;
        if (valid) {
            j = g_candJ[r * CCAP + p];
            const float4* row = (const float4*)(hn + j * DIM);
            float4 av[16];
            #pragma unroll
            for (int q = 0; q < 16; q++) av[q] = row[q];
            const float4* own = (const float4*)sR[w];
            #pragma unroll
            for (int q = 0; q < 16; q++) {
                float4 b4 = own[q];
                s += av[q].x * b4.x + av[q].y * b4.y
                   + av[q].z * b4.z + av[q].w * b4.w;
            }
        }
        bool surv = valid && (s >= 0.5f);
        uint32_t bal = __ballot_sync(0xffffffffu, surv);
        int rank = __popc(bal & ((1u << l) - 1u));
        if (surv) {
            int pos = cnt + rank;
            if (pos < SCAP) {
                sK[w][pos] = (((unsigned long long)__float_as_uint(s)) << 32)
                           | (uint32_t)(8191 - j);
                atomicOr(&sMask[w][j >> 5], 1u << (j & 31));
            }
        }
        cnt += __popc(bal);
    }
    __syncwarp();
    if (cnt > SCAP) cnt = SCAP;
    int nsel = cnt < TOPK ? cnt : TOPK;

    // rank-by-counting: each lane ranks its keys against all (broadcast LDS)
    for (int p = l; p < cnt; p += 32) {
        unsigned long long k = sK[w][p];
        int rank = 0;
        for (int q = 0; q < cnt; q++)
            rank += (sK[w][q] > k) ? 1 : 0;
        if (rank < TOPK) {
            int j = 8191 - (int)(uint32_t)(k & 0xFFFFFFFFu);
            H[rank * NN + j] = 1.0f;
        }
    }
    __syncwarp();

    // fill remaining slots with zeros (ascending j, skipping survivors)
    int s = nsel;
    for (int c = 0; c < 256 && s < TOPK; c++) {
        uint32_t word = sMask[w][c];
        uint32_t zmask = ~word;
        int nz = __popc(zmask);
        int take = TOPK - s; if (take > nz) take = nz;
        int rank = __popc(zmask & ((1u << l) - 1u));
        if (!((word >> l) & 1u) && rank < take)
            H[(s + rank) * NN + (c * 32 + l)] = 1.0f;
        s += nz;
    }
}

// ---------------------------------------------------------------------------
extern "C" void kernel_launch(void* const* d_in, const int* in_sizes, int n_in,
                              void* d_out, int out_size)
{
    const int* idx    = (const int*)d_in[0];
    const float* emb  = (const float*)d_in[1];
    const float* W    = (const float*)d_in[2];
    const float* bias = (const float*)d_in[3];
    float* H          = (float*)d_out;

    hn_kernel<<<NN / 64, 256>>>(idx, emb, W, bias, H);
    sim_mma_kernel<<<NJOBS, 256>>>();
    topk_kernel<<<NN / 8, 256>>>(H);
}

// round 17
// speedup vs baseline: 1.8678x; 1.0594x over previous
#include <cuda_runtime.h>
#include <cuda_bf16.h>
#include <math.h>
#include <stdint.h>

#define NN    8192
#define DIM   64
#define TOPK  64
#define CCAP  256
#define SCAP  160
#define SCREEN 0.49f
#define TS    128
#define PAD   72
#define NTILE (NN / TS)
#define NJOBS (NTILE * (NTILE + 1) / 2)

__device__ float         g_hn[NN * DIM];
__device__ __nv_bfloat16 g_hnbf[NN * DIM];
__device__ int           g_candJ[NN * CCAP];
__device__ int           g_ccnt[NN];

// ---------------------------------------------------------------------------
__device__ __forceinline__ uint32_t smem_u32(const void* p) {
    uint32_t a;
    asm("{ .reg .u64 t; cvta.to.shared.u64 t, %1; cvt.u32.u64 %0, t; }"
        : "=r"(a) : "l"(p));
    return a;
}
__device__ __forceinline__ void ldsm4(uint32_t* r, uint32_t addr) {
    asm volatile("ldmatrix.sync.aligned.m8n8.x4.shared.b16 {%0,%1,%2,%3}, [%4];"
                 : "=r"(r[0]), "=r"(r[1]), "=r"(r[2]), "=r"(r[3]) : "r"(addr));
}
__device__ __forceinline__ void mma16816(float* c, const uint32_t* a, const uint32_t* b) {
    asm volatile(
        "mma.sync.aligned.m16n8k16.row.col.f32.bf16.bf16.f32 "
        "{%0,%1,%2,%3}, {%4,%5,%6,%7}, {%8,%9}, {%0,%1,%2,%3};"
        : "+f"(c[0]), "+f"(c[1]), "+f"(c[2]), "+f"(c[3])
        : "r"(a[0]), "r"(a[1]), "r"(a[2]), "r"(a[3]), "r"(b[0]), "r"(b[1]));
}

// ---------------------------------------------------------------------------
// Kernel 1: hn — REVERTED to the R15 512-blocks x 16-rows version (measured
// 14.0us across four benches; the R16 fat-block variant regressed to 22.5us).
// Also zeroes H and g_ccnt. idx is int32.
// ---------------------------------------------------------------------------
__global__ void __launch_bounds__(256) hn_kernel(
    const int* __restrict__ idx,
    const float* __restrict__ emb,
    const float* __restrict__ W,
    const float* __restrict__ bias,
    float* __restrict__ H)
{
    __shared__ float WsT[64 * 72];
    __shared__ float xs[16][64];
    __shared__ int   s_src[16];
    __shared__ float s_bias[64];

    int t = threadIdx.x;

    ((float4*)H)[blockIdx.x * 256 + t] = make_float4(0.f, 0.f, 0.f, 0.f);
    if (blockIdx.x < 8)
        ((int4*)g_ccnt)[blockIdx.x * 256 + t] = make_int4(0, 0, 0, 0);

    if (t < 16) s_src[t] = idx[blockIdx.x * 16 + t] & (NN - 1);
    if (t < 64) s_bias[t] = bias[t];

    #pragma unroll
    for (int q = 0; q < 16; q++) {
        int e = q * 256 + t;
        WsT[(e & 63) * 72 + (e >> 6)] = W[e];
    }
    __syncthreads();

    #pragma unroll
    for (int q = 0; q < 4; q++) {
        int e = q * 256 + t;
        int r = e >> 6, k = e & 63;
        xs[r][k] = emb[s_src[r] * DIM + k];
    }
    __syncthreads();

    int r  = t >> 4;
    int d0 = (t & 15) * 4;

    float a0 = s_bias[d0], a1 = s_bias[d0 + 1], a2 = s_bias[d0 + 2], a3 = s_bias[d0 + 3];
    #pragma unroll
    for (int k = 0; k < 64; k++) {
        float  xv = xs[r][k];
        float4 w4 = *(const float4*)&WsT[k * 72 + d0];
        a0 += xv * w4.x; a1 += xv * w4.y; a2 += xv * w4.z; a3 += xv * w4.w;
    }

    float h0 = tanhf(3.0f * a0), h1 = tanhf(3.0f * a1);
    float h2 = tanhf(3.0f * a2), h3 = tanhf(3.0f * a3);

    float sq = h0 * h0 + h1 * h1 + h2 * h2 + h3 * h3;
    #pragma unroll
    for (int o = 8; o; o >>= 1)
        sq += __shfl_xor_sync(0xffffffffu, sq, o);

    float nrm = fmaxf(sqrtf(sq), 1e-8f);
    float v0 = h0 / nrm, v1 = h1 / nrm, v2 = h2 / nrm, v3 = h3 / nrm;

    int row = blockIdx.x * 16 + r;
    *(float4*)&g_hn[row * DIM + d0] = make_float4(v0, v1, v2, v3);

    __nv_bfloat162* bp = (__nv_bfloat162*)&g_hnbf[row * DIM + d0];
    bp[0] = __nv_bfloat162(__float2bfloat16(v0), __float2bfloat16(v1));
    bp[1] = __nv_bfloat162(__float2bfloat16(v2), __float2bfloat16(v3));
}

// ---------------------------------------------------------------------------
// Kernel 2: bf16 HMMA screen + aggregated epilogue (unchanged — R15/R16 win)
// ---------------------------------------------------------------------------
__global__ void __launch_bounds__(256) sim_mma_kernel()
{
    __shared__ __nv_bfloat16 sA[TS * PAD];
    __shared__ __nv_bfloat16 sB[TS * PAD];

    int b = blockIdx.x, ti = 0;
    while (b >= NTILE - ti) { b -= NTILE - ti; ti++; }
    int tj = ti + b;
    int ib = ti * TS, jb = tj * TS;

    int t = threadIdx.x, wid = t >> 5, l = t & 31;

    const __nv_bfloat16* hb = g_hnbf;
    #pragma unroll
    for (int q = 0; q < 4; q++) {
        int id  = q * 256 + t;
        int row = id >> 3, c8 = (id & 7) * 8;
        *(uint4*)(sA + row * PAD + c8) = *(const uint4*)(hb + (ib + row) * DIM + c8);
        *(uint4*)(sB + row * PAD + c8) = *(const uint4*)(hb + (jb + row) * DIM + c8);
    }
    __syncthreads();

    int wr = wid >> 2, wc = wid & 3;
    int R0 = wr * 64, C0 = wc * 32;

    float acc[4][4][4];
    #pragma unroll
    for (int mt = 0; mt < 4; mt++)
        #pragma unroll
        for (int nt = 0; nt < 4; nt++)
            #pragma unroll
            for (int e = 0; e < 4; e++) acc[mt][nt][e] = 0.0f;

    uint32_t aBase = smem_u32(sA);
    uint32_t bBase = smem_u32(sB);

    int lr    = l & 7;
    int khalf = (l >> 3) & 1;
    int kq    = l >> 4;

    #pragma unroll
    for (int ks = 0; ks < 4; ks++) {
        int k0 = ks * 16;

        uint32_t af[4][4];
        #pragma unroll
        for (int mt = 0; mt < 4; mt++) {
            uint32_t addr = aBase +
                (uint32_t)(((R0 + mt * 16 + lr + khalf * 8) * PAD + k0 + kq * 8) * 2);
            ldsm4(af[mt], addr);
        }

        uint32_t bf[4][2];
        #pragma unroll
        for (int np = 0; np < 2; np++) {
            uint32_t r4[4];
            uint32_t addr = bBase +
                (uint32_t)(((C0 + np * 16 + kq * 8 + lr) * PAD + k0 + khalf * 8) * 2);
            ldsm4(r4, addr);
            bf[np * 2 + 0][0] = r4[0]; bf[np * 2 + 0][1] = r4[1];
            bf[np * 2 + 1][0] = r4[2]; bf[np * 2 + 1][1] = r4[3];
        }

        #pragma unroll
        for (int mt = 0; mt < 4; mt++)
            #pragma unroll
            for (int nt = 0; nt < 4; nt++)
                mma16816(acc[mt][nt], af[mt], bf[nt]);
    }

    bool diag = (ti == tj);
    int gr = l >> 2, tg = l & 3;
    int colBase = jb + C0 + tg * 2;

    #pragma unroll
    for (int mt = 0; mt < 4; mt++) {
        #pragma unroll
        for (int rh = 0; rh < 2; rh++) {
            int gi = ib + R0 + mt * 16 + gr + rh * 8;
            uint32_t mask = 0;
            #pragma unroll
            for (int nt = 0; nt < 4; nt++) {
                #pragma unroll
                for (int eb = 0; eb < 2; eb++) {
                    float v = acc[mt][nt][rh * 2 + eb];
                    int gj = colBase + nt * 8 + eb;
                    bool cond = (v >= SCREEN) && (!diag || gj >= gi);
                    mask |= (cond ? 1u : 0u) << (nt * 2 + eb);
                }
            }
            if (mask) {
                int n = __popc(mask);
                int base = atomicAdd(&g_ccnt[gi], n);
                while (mask) {
                    int bit = __ffs(mask) - 1;
                    mask &= mask - 1;
                    int gj = colBase + (bit >> 1) * 8 + (bit & 1);
                    if (base < CCAP) g_candJ[gi * CCAP + base] = gj;
                    base++;
                }
            }
        }
    }
    #pragma unroll
    for (int nt = 0; nt < 4; nt++) {
        #pragma unroll
        for (int eb = 0; eb < 2; eb++) {
            int gj = colBase + nt * 8 + eb;
            uint32_t mask = 0;
            #pragma unroll
            for (int mt = 0; mt < 4; mt++) {
                #pragma unroll
                for (int rh = 0; rh < 2; rh++) {
                    float v = acc[mt][nt][rh * 2 + eb];
                    int gi = ib + R0 + mt * 16 + gr + rh * 8;
                    bool cond = (v >= SCREEN) && (!diag || gj > gi);
                    mask |= (cond ? 1u : 0u) << (mt * 2 + rh);
                }
            }
            if (mask) {
                int n = __popc(mask);
                int base = atomicAdd(&g_ccnt[gj], n);
                while (mask) {
                    int bit = __ffs(mask) - 1;
                    mask &= mask - 1;
                    int gi = ib + R0 + (bit >> 1) * 16 + gr + (bit & 1) * 8;
                    if (base < CCAP) g_candJ[gj * CCAP + base] = gi;
                    base++;
                }
            }
        }
    }
}

// ---------------------------------------------------------------------------
// Kernel 3: parallel recheck + rank-by-counting top-64 + bitmask fill
// (unchanged — R16 win)
// ---------------------------------------------------------------------------
__global__ void __launch_bounds__(256) topk_kernel(float* __restrict__ H)
{
    __shared__ float              sR[8][64];
    __shared__ unsigned long long sK[8][SCAP];
    __shared__ uint32_t           sMask[8][256];

    int t = threadIdx.x, w = t >> 5, l = t & 31;
    int r = blockIdx.x * 8 + w;
    const float* __restrict__ hn = g_hn;

    sR[w][l]      = hn[r * DIM + l];
    sR[w][32 + l] = hn[r * DIM + 32 + l];
    #pragma unroll
    for (int c = 0; c < 8; c++) sMask[w][c * 32 + l] = 0;
    __syncwarp();

    int m = g_ccnt[r];
    if (m > CCAP) m = CCAP;

    int cnt = 0;
    for (int base = 0; base < m; base += 32) {
        int p = base + l;
        bool valid = p < m;
        int j = 0;
        float s = 0.0f;
        if (valid) {
            j = g_candJ[r * CCAP + p];
            const float4* row = (const float4*)(hn + j * DIM);
            float4 av[16];
            #pragma unroll
            for (int q = 0; q < 16; q++) av[q] = row[q];
            const float4* own = (const float4*)sR[w];
            #pragma unroll
            for (int q = 0; q < 16; q++) {
                float4 b4 = own[q];
                s += av[q].x * b4.x + av[q].y * b4.y
                   + av[q].z * b4.z + av[q].w * b4.w;
            }
        }
        bool surv = valid && (s >= 0.5f);
        uint32_t bal = __ballot_sync(0xffffffffu, surv);
        int rank = __popc(bal & ((1u << l) - 1u));
        if (surv) {
            int pos = cnt + rank;
            if (pos < SCAP) {
                sK[w][pos] = (((unsigned long long)__float_as_uint(s)) << 32)
                           | (uint32_t)(8191 - j);
                atomicOr(&sMask[w][j >> 5], 1u << (j & 31));
            }
        }
        cnt += __popc(bal);
    }
    __syncwarp();
    if (cnt > SCAP) cnt = SCAP;
    int nsel = cnt < TOPK ? cnt : TOPK;

    for (int p = l; p < cnt; p += 32) {
        unsigned long long k = sK[w][p];
        int rank = 0;
        for (int q = 0; q < cnt; q++)
            rank += (sK[w][q] > k) ? 1 : 0;
        if (rank < TOPK) {
            int j = 8191 - (int)(uint32_t)(k & 0xFFFFFFFFu);
            H[rank * NN + j] = 1.0f;
        }
    }
    __syncwarp();

    int s = nsel;
    for (int c = 0; c < 256 && s < TOPK; c++) {
        uint32_t word = sMask[w][c];
        uint32_t zmask = ~word;
        int nz = __popc(zmask);
        int take = TOPK - s; if (take > nz) take = nz;
        int rank = __popc(zmask & ((1u << l) - 1u));
        if (!((word >> l) & 1u) && rank < take)
            H[(s + rank) * NN + (c * 32 + l)] = 1.0f;
        s += nz;
    }
}

// ---------------------------------------------------------------------------
extern "C" void kernel_launch(void* const* d_in, const int* in_sizes, int n_in,
                              void* d_out, int out_size)
{
    const int* idx    = (const int*)d_in[0];
    const float* emb  = (const float*)d_in[1];
    const float* W    = (const float*)d_in[2];
    const float* bias = (const float*)d_in[3];
    float* H          = (float*)d_out;

    hn_kernel<<<NN / 16, 256>>>(idx, emb, W, bias, H);
    sim_mma_kernel<<<NJOBS, 256>>>();
    topk_kernel<<<NN / 8, 256>>>(H);
}